// round 3
// baseline (speedup 1.0000x reference)
#include <cuda_runtime.h>
#include <math.h>

// ---------------- problem constants ----------------
#define NI      16          // instances = N_CLASSES(2) * B(8); iid = class*8 + b
#define HW      409600      // 640*640
#define HW4     102400      // HW/4
#define NCH     12
#define NMAPS   6
#define EPSF    1e-4
#define BPI     18          // blocks per instance
#define NB      (NI*BPI)    // 288 blocks total (<= 296 = 148 SMs * 2 -> all co-resident)

// ---------------- device scratch (static; no runtime allocation) ----------------
__device__ unsigned g_bar;                    // grid barrier counter (reset by k_init)
__device__ unsigned g_pos[NI], g_neg[NI];
__device__ int      g_mode[NI];               // 0=select-all(A) 1=fallback(B) 2=hist
__device__ int      g_anyhist;
__device__ unsigned long long g_k[NI];
__device__ float    g_thr[NI];
__device__ unsigned g_selhi[NI], g_krem[NI];
__device__ unsigned g_histhi[NI][8192];       // top-13-bit histogram (rare path; stays zero)
__device__ unsigned g_histlo[NI][524288];     // low-19-bit histogram (rare path; stays zero)
// sums layout: [0..2]=text variant A (a,b,c)  [3..5]=text variant B  [6..10]=a_k  [11..15]=b_k  [16..20]=c_k
__device__ double   g_sums[NI][21];
__device__ double   g_fix[NI][3];             // exact text sums on hist path

// ---------------- helpers ----------------
__device__ __forceinline__ float fsigmoid(float x) {
    float t;
    asm("tanh.approx.f32 %0, %1;" : "=f"(t) : "f"(0.5f * x));
    return fmaf(0.5f, t, 0.5f);
}
__device__ __forceinline__ unsigned keyOf(float x) {
    unsigned u = __float_as_uint(x);
    return (u & 0x80000000u) ? ~u : (u | 0x80000000u);
}
__device__ __forceinline__ float unkey(unsigned k) {
    unsigned u = (k & 0x80000000u) ? (k ^ 0x80000000u) : ~k;
    return __uint_as_float(u);
}

// monotonic software grid barrier; all NB blocks resident by construction
__device__ __forceinline__ void gridbar(int phase) {
    __syncthreads();
    __threadfence();
    if (threadIdx.x == 0) {
        atomicAdd(&g_bar, 1u);
        unsigned tgt = (unsigned)phase * (unsigned)NB;
        while (*(volatile unsigned*)&g_bar < tgt) { }
    }
    __syncthreads();
    __threadfence();
}

// ---------------- finalize (runs on one thread) ----------------
__device__ void finalize_write(float* out) {
    double ltc[2] = {0.0, 0.0}, lkc[2] = {0.0, 0.0};
    for (int t = 0; t < NI; t++) {
        int cls = t >> 3;
        int mode = *(volatile int*)&g_mode[t];
        double a, bb, cc;
        if (mode == 2)      { a = g_fix[t][0];  bb = g_fix[t][1];  cc = g_fix[t][2]; }
        else if (mode == 1) { a = g_sums[t][3]; bb = g_sums[t][4]; cc = g_sums[t][5]; }
        else                { a = g_sums[t][0]; bb = g_sums[t][1]; cc = g_sums[t][2]; }
        double lt = 1.0 - 2.0 * a / ((bb + EPSF) + (cc + EPSF));
        double lk = 0.0;
        for (int j = 0; j < 5; j++) {
            double aj = g_sums[t][6 + j];
            double bj = g_sums[t][11 + j] + EPSF;
            double cj = g_sums[t][16 + j] + EPSF;
            lk += 1.0 - 2.0 * aj / (bj + cj);
        }
        lk *= 0.2;
        ltc[cls] += lt; lkc[cls] += lk;
    }
    double lt0 = ltc[0] * 0.125, lt1 = ltc[1] * 0.125;
    double lk0 = lkc[0] * 0.125, lk1 = lkc[1] * 0.125;
    double l0 = 0.7 * lt0 + 0.3 * lk0;
    double l1 = 0.7 * lt1 + 0.3 * lk1;
    out[0] = (float)(0.5 * (l0 + l1));
    out[1] = (float)(0.5 * (lt0 + lt1));
    out[2] = (float)(0.5 * (lk0 + lk1));
}

// ---------------- kernel: reset per-run scratch ----------------
__global__ void k_init() {
    int t = threadIdx.x;
    if (t == 0) { g_bar = 0u; g_anyhist = 0; }
    if (t < NI) { g_pos[t] = 0u; g_neg[t] = 0u; }
    double* s = &g_sums[0][0];
    for (int i = t; i < NI * 21; i += blockDim.x) s[i] = 0.0;
    double* f = &g_fix[0][0];
    for (int i = t; i < NI * 3; i += blockDim.x) f[i] = 0.0;
}

// ---------------- the mega kernel ----------------
__global__ void __launch_bounds__(256, 2) k_mega(const float* __restrict__ outs,
                                                 const float* __restrict__ labs,
                                                 const float* __restrict__ tmg,
                                                 float* __restrict__ out) {
    const int blk = blockIdx.x;
    const int inst_lin = blk / BPI;       // interleaved: (b<<1)|i  -> tm L2 reuse
    const int slice = blk % BPI;
    const int b = inst_lin >> 1, i = inst_lin & 1;
    const int iid = i * 8 + b;            // class-major instance id
    const int tid = threadIdx.x;

    const float4* ob = (const float4*)outs + ((size_t)b * NCH + i * NMAPS) * HW4;
    const float4* lb = (const float4*)labs + ((size_t)b * NCH + i * NMAPS) * HW4;
    const float4* m4 = (const float4*)tmg + (size_t)b * HW4;

    // ======== phase 1: single fused pass (counts + all dice partial sums) ========
    float acc[21];
    #pragma unroll
    for (int j = 0; j < 21; j++) acc[j] = 0.f;
    unsigned pos = 0, neg = 0;

    for (int idx = slice * 256 + tid; idx < HW4; idx += NB / NI * 256) {
        float4 tq = ob[5 * HW4 + idx];
        float4 gq = lb[5 * HW4 + idx];
        float4 mq = m4[idx];
        float tv[4] = {tq.x, tq.y, tq.z, tq.w};
        float gv[4] = {gq.x, gq.y, gq.z, gq.w};
        float mv[4] = {mq.x, mq.y, mq.z, mq.w};
        float wk[4];
        #pragma unroll
        for (int e = 0; e < 4; e++) {
            float sc = tv[e], gt = gv[e], tm = mv[e];
            bool tmb = tm > 0.5f;
            if (gt > 0.5f) { if (tmb) pos++; }
            else neg++;
            float sg = fsigmoid(sc);
            float b0 = sg * gt, b1 = sg * sg, b2 = gt * gt;
            float wA = tmb ? 1.f : 0.f;
            float wB = tm * tm;
            acc[0] = fmaf(wA, b0, acc[0]);
            acc[1] = fmaf(wA, b1, acc[1]);
            acc[2] = fmaf(wA, b2, acc[2]);
            acc[3] = fmaf(wB, b0, acc[3]);
            acc[4] = fmaf(wB, b1, acc[4]);
            acc[5] = fmaf(wB, b2, acc[5]);
            wk[e] = (sc > 0.f && tmb) ? 1.f : 0.f;
        }
        #pragma unroll
        for (int j = 0; j < 5; j++) {
            float4 kq = ob[(size_t)j * HW4 + idx];
            float4 gk = lb[(size_t)j * HW4 + idx];
            float kv[4] = {kq.x, kq.y, kq.z, kq.w};
            float gw[4] = {gk.x, gk.y, gk.z, gk.w};
            #pragma unroll
            for (int e = 0; e < 4; e++) {
                float sg = fsigmoid(kv[e]);
                float w = wk[e];
                acc[6 + j]  = fmaf(w, sg * gw[e],    acc[6 + j]);
                acc[11 + j] = fmaf(w, sg * sg,       acc[11 + j]);
                acc[16 + j] = fmaf(w, gw[e] * gw[e], acc[16 + j]);
            }
        }
    }

    // block reduce 21 floats + 2 uints
    #pragma unroll
    for (int j = 0; j < 21; j++) {
        float v = acc[j];
        #pragma unroll
        for (int o = 16; o; o >>= 1) v += __shfl_down_sync(0xffffffffu, v, o);
        acc[j] = v;
    }
    #pragma unroll
    for (int o = 16; o; o >>= 1) {
        pos += __shfl_down_sync(0xffffffffu, pos, o);
        neg += __shfl_down_sync(0xffffffffu, neg, o);
    }
    __shared__ float bsum[21];
    __shared__ unsigned bpos, bneg;
    if (tid < 21) bsum[tid] = 0.f;
    if (tid == 0) { bpos = 0u; bneg = 0u; }
    __syncthreads();
    if ((tid & 31) == 0) {
        #pragma unroll
        for (int j = 0; j < 21; j++) atomicAdd(&bsum[j], acc[j]);
        atomicAdd(&bpos, pos); atomicAdd(&bneg, neg);
    }
    __syncthreads();
    if (tid < 21) atomicAdd(&g_sums[iid][tid], (double)bsum[tid]);
    if (tid == 21) atomicAdd(&g_pos[iid], bpos);
    if (tid == 22) atomicAdd(&g_neg[iid], bneg);

    gridbar(1);

    // ======== decide (block 0) ; fast-path finalize happens right here ========
    if (blk == 0) {
        if (tid < NI) {
            unsigned p = g_pos[tid], n = g_neg[tid];
            unsigned long long k = (unsigned long long)p * 3ull;
            if (k > n) k = n;
            int mode;
            if (p == 0u || k == 0ull) mode = 1;        // fallback -> variant B
            else if (k == (unsigned long long)n) mode = 0;  // select-all -> variant A
            else mode = 2;                              // exact radix select
            g_mode[tid] = mode;
            g_k[tid] = k;
            if (mode == 2) atomicExch(&g_anyhist, 1);
        }
        __syncthreads();
        if (tid == 0 && *(volatile int*)&g_anyhist == 0) finalize_write(out);
    }

    gridbar(2);
    if (*(volatile int*)&g_anyhist == 0) return;

    // =================== rare exact-select path (uniform branch) ===================
    const int mymode = *(volatile int*)&g_mode[iid];
    const int ch = i * NMAPS + (NMAPS - 1);
    const float4* sc4 = (const float4*)outs + ((size_t)b * NCH + ch) * HW4;
    const float4* gt4 = (const float4*)labs + ((size_t)b * NCH + ch) * HW4;

    __shared__ unsigned shist[8192];
    __shared__ unsigned long long csum[256];

    // phase: hi histogram (top 13 bits of order-key)
    if (mymode == 2) {
        for (int j2 = tid; j2 < 8192; j2 += 256) shist[j2] = 0u;
        __syncthreads();
        for (int idx = slice * 256 + tid; idx < HW4; idx += BPI * 256) {
            float4 s = sc4[idx]; float4 g = gt4[idx];
            float sv[4] = {s.x, s.y, s.z, s.w};
            float gg[4] = {g.x, g.y, g.z, g.w};
            #pragma unroll
            for (int e = 0; e < 4; e++)
                if (gg[e] <= 0.5f) atomicAdd(&shist[keyOf(sv[e]) >> 19], 1u);
        }
        __syncthreads();
        for (int j2 = tid; j2 < 8192; j2 += 256) {
            unsigned c = shist[j2];
            if (c) atomicAdd(&g_histhi[iid][j2], c);
        }
    }
    gridbar(3);

    // phase: scan hi descending (block t scans instance t)
    if (blk < NI && *(volatile int*)&g_mode[blk] == 2) {
        unsigned long long s = 0;
        int hi = 8192 - tid * 32;
        for (int bn = hi - 1; bn >= hi - 32; bn--) s += g_histhi[blk][bn];
        csum[tid] = s;
        __syncthreads();
        if (tid == 0) {
            unsigned long long k = g_k[blk], cum = 0;
            for (int c = 0; c < 256; c++) {
                if (cum + csum[c] >= k) {
                    int h2 = 8192 - c * 32;
                    for (int bn = h2 - 1; bn >= h2 - 32; bn--) {
                        unsigned long long hv = g_histhi[blk][bn];
                        if (cum + hv >= k) { g_selhi[blk] = (unsigned)bn; g_krem[blk] = (unsigned)(k - cum); goto donehi; }
                        cum += hv;
                    }
                }
                cum += csum[c];
            }
            donehi: ;
        }
    }
    gridbar(4);

    // phase: lo histogram (low 19 bits among matching hi-bin)
    if (mymode == 2) {
        unsigned sel = *(volatile unsigned*)&g_selhi[iid];
        for (int idx = slice * 256 + tid; idx < HW4; idx += BPI * 256) {
            float4 s = sc4[idx]; float4 g = gt4[idx];
            float sv[4] = {s.x, s.y, s.z, s.w};
            float gg[4] = {g.x, g.y, g.z, g.w};
            #pragma unroll
            for (int e = 0; e < 4; e++) {
                if (gg[e] <= 0.5f) {
                    unsigned kk = keyOf(sv[e]);
                    if ((kk >> 19) == sel) atomicAdd(&g_histlo[iid][kk & 0x7FFFFu], 1u);
                }
            }
        }
    }
    gridbar(5);

    // phase: scan lo descending -> exact threshold
    if (blk < NI && *(volatile int*)&g_mode[blk] == 2) {
        unsigned long long s = 0;
        int hi = 524288 - tid * 2048;
        for (int bn = hi - 1; bn >= hi - 2048; bn--) s += g_histlo[blk][bn];
        csum[tid] = s;
        __syncthreads();
        if (tid == 0) {
            unsigned long long k = (unsigned long long)g_krem[blk], cum = 0;
            unsigned sel = g_selhi[blk];
            for (int c = 0; c < 256; c++) {
                if (cum + csum[c] >= k) {
                    int h2 = 524288 - c * 2048;
                    for (int bn = h2 - 1; bn >= h2 - 2048; bn--) {
                        unsigned long long hv = g_histlo[blk][bn];
                        if (cum + hv >= k) { g_thr[blk] = unkey((sel << 19) | (unsigned)bn); goto donelo; }
                        cum += hv;
                    }
                }
                cum += csum[c];
            }
            donelo: ;
        }
    }
    gridbar(6);

    // phase: exact text dice sums with real threshold + cleanup hists for next run
    if (mymode == 2) {
        float thr = *(volatile float*)&g_thr[iid];
        float a0 = 0.f, a1 = 0.f, a2 = 0.f;
        for (int idx = slice * 256 + tid; idx < HW4; idx += BPI * 256) {
            float4 s = sc4[idx]; float4 g = gt4[idx]; float4 m = m4[idx];
            float sv[4] = {s.x, s.y, s.z, s.w};
            float gg[4] = {g.x, g.y, g.z, g.w};
            float mm[4] = {m.x, m.y, m.z, m.w};
            #pragma unroll
            for (int e = 0; e < 4; e++) {
                float st = (((sv[e] >= thr) || (gg[e] > 0.5f)) && (mm[e] > 0.5f)) ? 1.f : 0.f;
                float sg = fsigmoid(sv[e]);
                a0 = fmaf(st, sg * gg[e], a0);
                a1 = fmaf(st, sg * sg, a1);
                a2 = fmaf(st, gg[e] * gg[e], a2);
            }
        }
        #pragma unroll
        for (int o = 16; o; o >>= 1) {
            a0 += __shfl_down_sync(0xffffffffu, a0, o);
            a1 += __shfl_down_sync(0xffffffffu, a1, o);
            a2 += __shfl_down_sync(0xffffffffu, a2, o);
        }
        __shared__ float fx[3];
        if (tid < 3) fx[tid] = 0.f;
        __syncthreads();
        if ((tid & 31) == 0) {
            atomicAdd(&fx[0], a0); atomicAdd(&fx[1], a1); atomicAdd(&fx[2], a2);
        }
        __syncthreads();
        if (tid < 3) atomicAdd(&g_fix[iid][tid], (double)fx[tid]);
    }
    // clear histograms (only dirtied on this path)
    {
        unsigned* hi2 = &g_histhi[0][0];
        unsigned* lo2 = &g_histlo[0][0];
        int gt0 = blk * 256 + tid, gs = NB * 256;
        for (int j2 = gt0; j2 < NI * 8192; j2 += gs) hi2[j2] = 0u;
        for (size_t j2 = gt0; j2 < (size_t)NI * 524288; j2 += gs) lo2[j2] = 0u;
    }
    gridbar(7);

    if (blk == 0 && tid == 0) finalize_write(out);
}

// ---------------- launch ----------------
extern "C" void kernel_launch(void* const* d_in, const int* in_sizes, int n_in,
                              void* d_out, int out_size) {
    const float* outs = (const float*)d_in[0];
    const float* labs = (const float*)d_in[1];
    const float* tmg  = (const float*)d_in[2];
    float* out = (float*)d_out;

    k_init<<<1, 256>>>();
    k_mega<<<NB, 256>>>(outs, labs, tmg, out);
}